// round 7
// baseline (speedup 1.0000x reference)
#include <cuda_runtime.h>
#include <cuda_bf16.h>
#include <cstdint>

// Loss_Labels: -mean over B of ( label==1 ? log_softmax(s,a)[0]
//                              : label==2 ? log_softmax(s,a)[1] : 0 )
//
// Labels int32 on device. 12 B/element, ~100 MB streamed. R7: fight the
// multi-CTA completion spread (B300: high MLP_p1 + one-wave grid -> up to 2x
// CTA spread, and our last-block finalize waits on the SLOWEST CTA):
//  - low-MLP body (3 front-batched 128-bit loads), regs ~30, occ 8
//  - grid = 2 full waves (2368 blocks) -> wave-2 work-stealing rebalances
//  - __ldcs evict-first streaming loads (zero reuse)
//  - warp-shuffle epilogue (fixed-order, deterministic)
// Fused in-kernel finalize, single launch.

#define NSM 148
#define NB  (NSM * 8 * 2)   // 2368 blocks: two exact waves at 8 blocks/SM
#define NT  256
#define NWARP (NT / 32)

__device__ float g_partials[NB];
__device__ unsigned int g_done_count;   // zero-init; reset by last block

__device__ __forceinline__ float err_term(float s, float a, int lab) {
    // d = a - s; lse - s = max(d,0) + log(1 + exp(-|d|))  (arg in (1,2])
    float d = a - s;
    float t = fmaxf(d, 0.0f) + __logf(1.0f + __expf(-fabsf(d)));
    return (lab == 1) ? -t : ((lab == 2) ? (d - t) : 0.0f);
}

// Deterministic fixed-order block reduction: warp shuffles + one smem pass.
__device__ __forceinline__ float block_reduce(float v, float* smw) {
    const int lane = threadIdx.x & 31;
    const int wid  = threadIdx.x >> 5;
#pragma unroll
    for (int off = 16; off > 0; off >>= 1)
        v += __shfl_down_sync(0xffffffffu, v, off);
    if (lane == 0) smw[wid] = v;
    __syncthreads();
    if (wid == 0) {
        v = (lane < NWARP) ? smw[lane] : 0.0f;
#pragma unroll
        for (int off = NWARP / 2; off > 0; off >>= 1)
            v += __shfl_down_sync(0xffffffffu, v, off);
    }
    return v;   // valid in (wid==0, lane==0)
}

__global__ void __launch_bounds__(NT, 8)
loss_fused_kernel(const float4* __restrict__ s4,
                  const float4* __restrict__ a4,
                  const int4*   __restrict__ l4,
                  float* __restrict__ out,
                  int n, int nvec)
{
    float acc = 0.0f;
    const int stride = gridDim.x * blockDim.x;
    for (int i = blockIdx.x * blockDim.x + threadIdx.x; i < nvec; i += stride) {
        float4 s = __ldcs(&s4[i]);
        float4 a = __ldcs(&a4[i]);
        int4   l = __ldcs(&l4[i]);
        acc += err_term(s.x, a.x, l.x);
        acc += err_term(s.y, a.y, l.y);
        acc += err_term(s.z, a.z, l.z);
        acc += err_term(s.w, a.w, l.w);
    }

    // scalar tail (n % 4 != 0); n = 8388608 divisible, kept for safety
    if (blockIdx.x == 0) {
        const float* s = (const float*)s4;
        const float* a = (const float*)a4;
        const int*   l = (const int*)l4;
        for (int t = nvec * 4 + threadIdx.x; t < n; t += NT)
            acc += err_term(s[t], a[t], l[t]);
    }

    __shared__ float smw[NWARP];
    float bsum = block_reduce(acc, smw);

    __shared__ bool s_last;
    if (threadIdx.x == 0) {
        g_partials[blockIdx.x] = bsum;
        __threadfence();
        unsigned int prev = atomicAdd(&g_done_count, 1u);
        s_last = (prev == (unsigned int)(gridDim.x - 1));
    }
    __syncthreads();

    if (s_last) {
        __threadfence();  // all partials visible
        float facc = 0.0f;
        for (int k = threadIdx.x; k < NB; k += NT)
            facc += g_partials[k];
        __syncthreads();
        float total = block_reduce(facc, smw);
        if (threadIdx.x == 0) {
            out[0] = -total / (float)n;
            g_done_count = 0;   // reset for next graph replay
        }
    }
}

extern "C" void kernel_launch(void* const* d_in, const int* in_sizes, int n_in,
                              void* d_out, int out_size)
{
    const float* s   = (const float*)d_in[0];  // synonymy_score [B]
    const float* a   = (const float*)d_in[1];  // antonymy_score [B]
    const int*   lab = (const int*)d_in[2];    // labels [B] (int32 on device)
    float*       out = (float*)d_out;

    const int n    = in_sizes[0];
    const int nvec = n / 4;

    loss_fused_kernel<<<NB, NT>>>((const float4*)s, (const float4*)a,
                                  (const int4*)lab, out, n, nvec);
}

// round 8
// speedup vs baseline: 1.0375x; 1.0375x over previous
#include <cuda_runtime.h>
#include <cuda_bf16.h>
#include <cstdint>

// Loss_Labels: -mean over B of ( label==1 ? log_softmax(s,a)[0]
//                              : label==2 ? log_softmax(s,a)[1] : 0 )
//
// Labels int32 on device. 12 B/element, ~100 MB streamed.
// R8 = R5 body (simple float4 triple, default-cached loads, occ 8) with ONE
// change: grid = 2 exact waves (2368 CTAs). Wave-2 work-stealing rebalances
// CTA completion spread so the last-block finalize waits ~mean instead of
// ~max CTA time. Shuffle epilogue (fixed-order, deterministic).

#define NSM 148
#define NB  (NSM * 8 * 2)   // 2368 blocks: two exact waves at 8 blocks/SM
#define NT  256
#define NWARP (NT / 32)

__device__ float g_partials[NB];
__device__ unsigned int g_done_count;   // zero-init; reset by last block

__device__ __forceinline__ float err_term(float s, float a, int lab) {
    // d = a - s; lse - s = max(d,0) + log(1 + exp(-|d|))  (arg in (1,2])
    float d = a - s;
    float t = fmaxf(d, 0.0f) + __logf(1.0f + __expf(-fabsf(d)));
    return (lab == 1) ? -t : ((lab == 2) ? (d - t) : 0.0f);
}

// Deterministic fixed-order block reduction: warp shuffles + one smem pass.
__device__ __forceinline__ float block_reduce(float v, float* smw) {
    const int lane = threadIdx.x & 31;
    const int wid  = threadIdx.x >> 5;
#pragma unroll
    for (int off = 16; off > 0; off >>= 1)
        v += __shfl_down_sync(0xffffffffu, v, off);
    if (lane == 0) smw[wid] = v;
    __syncthreads();
    if (wid == 0) {
        v = (lane < NWARP) ? smw[lane] : 0.0f;
#pragma unroll
        for (int off = NWARP / 2; off > 0; off >>= 1)
            v += __shfl_down_sync(0xffffffffu, v, off);
    }
    return v;   // valid in (wid==0, lane==0)
}

__global__ void __launch_bounds__(NT, 8)
loss_fused_kernel(const float4* __restrict__ s4,
                  const float4* __restrict__ a4,
                  const int4*   __restrict__ l4,
                  float* __restrict__ out,
                  int n, int nvec)
{
    float acc = 0.0f;
    const int stride = gridDim.x * blockDim.x;
    for (int i = blockIdx.x * blockDim.x + threadIdx.x; i < nvec; i += stride) {
        float4 s = s4[i];
        float4 a = a4[i];
        int4   l = l4[i];
        acc += err_term(s.x, a.x, l.x);
        acc += err_term(s.y, a.y, l.y);
        acc += err_term(s.z, a.z, l.z);
        acc += err_term(s.w, a.w, l.w);
    }

    // scalar tail (n % 4 != 0); n = 8388608 divisible, kept for safety
    if (blockIdx.x == 0) {
        const float* s = (const float*)s4;
        const float* a = (const float*)a4;
        const int*   l = (const int*)l4;
        for (int t = nvec * 4 + threadIdx.x; t < n; t += NT)
            acc += err_term(s[t], a[t], l[t]);
    }

    __shared__ float smw[NWARP];
    float bsum = block_reduce(acc, smw);

    __shared__ bool s_last;
    if (threadIdx.x == 0) {
        g_partials[blockIdx.x] = bsum;
        __threadfence();
        unsigned int prev = atomicAdd(&g_done_count, 1u);
        s_last = (prev == (unsigned int)(gridDim.x - 1));
    }
    __syncthreads();

    if (s_last) {
        __threadfence();  // all partials visible
        float facc = 0.0f;
        for (int k = threadIdx.x; k < NB; k += NT)
            facc += g_partials[k];
        __syncthreads();
        float total = block_reduce(facc, smw);
        if (threadIdx.x == 0) {
            out[0] = -total / (float)n;
            g_done_count = 0;   // reset for next graph replay
        }
    }
}

extern "C" void kernel_launch(void* const* d_in, const int* in_sizes, int n_in,
                              void* d_out, int out_size)
{
    const float* s   = (const float*)d_in[0];  // synonymy_score [B]
    const float* a   = (const float*)d_in[1];  // antonymy_score [B]
    const int*   lab = (const int*)d_in[2];    // labels [B] (int32 on device)
    float*       out = (float*)d_out;

    const int n    = in_sizes[0];
    const int nvec = n / 4;

    loss_fused_kernel<<<NB, NT>>>((const float4*)s, (const float4*)a,
                                  (const int4*)lab, out, n, nvec);
}

// round 9
// speedup vs baseline: 1.1731x; 1.1307x over previous
#include <cuda_runtime.h>
#include <cuda_bf16.h>
#include <cstdint>

// Loss_Labels: -mean over B of ( label==1 ? log_softmax(s,a)[0]
//                              : label==2 ? log_softmax(s,a)[1] : 0 )
//
// Labels int32 on device. 12 B/element, ~100 MB streamed.
// R9 = R6 (pair body: 6 independent 128-bit loads front-batched, smem-tree
// epilogue, fused last-block finalize) with ONE change: occupancy 7 -> 8
// (grid 1184 = exactly one full wave at 8 blocks/SM; 32 regs * 2048 thr
// exactly fills the RF). Best wall so far: R6 = 18.9 us.

#define NSM 148
#define OCC 8
#define NB (NSM * OCC)   // 1184 blocks: one full wave at 8 blocks/SM
#define NT 256

__device__ float g_partials[NB];
__device__ unsigned int g_done_count;   // zero-init; reset by last block

__device__ __forceinline__ float err_term(float s, float a, int lab) {
    // d = a - s; lse - s = max(d,0) + log(1 + exp(-|d|))  (arg in (1,2])
    float d = a - s;
    float t = fmaxf(d, 0.0f) + __logf(1.0f + __expf(-fabsf(d)));
    return (lab == 1) ? -t : ((lab == 2) ? (d - t) : 0.0f);
}

__global__ void __launch_bounds__(NT, OCC)
loss_fused_kernel(const float4* __restrict__ s4,
                  const float4* __restrict__ a4,
                  const int4*   __restrict__ l4,
                  float* __restrict__ out,
                  int n, int nvec)
{
    const int npair  = nvec / 2;               // pairs of float4
    const int stride = gridDim.x * blockDim.x;

    float acc = 0.0f;
    for (int i = blockIdx.x * blockDim.x + threadIdx.x; i < npair; i += stride) {
        // 6 independent 128-bit loads, front-batched
        float4 s0 = s4[2 * i];
        float4 s1 = s4[2 * i + 1];
        float4 a0 = a4[2 * i];
        float4 a1 = a4[2 * i + 1];
        int4   l0 = l4[2 * i];
        int4   l1 = l4[2 * i + 1];

        acc += err_term(s0.x, a0.x, l0.x);
        acc += err_term(s0.y, a0.y, l0.y);
        acc += err_term(s0.z, a0.z, l0.z);
        acc += err_term(s0.w, a0.w, l0.w);
        acc += err_term(s1.x, a1.x, l1.x);
        acc += err_term(s1.y, a1.y, l1.y);
        acc += err_term(s1.z, a1.z, l1.z);
        acc += err_term(s1.w, a1.w, l1.w);
    }

    // scalar tail: elements [npair*8, n) (n = 8388608 -> empty; kept for safety)
    if (blockIdx.x == 0) {
        const float* s = (const float*)s4;
        const float* a = (const float*)a4;
        const int*   l = (const int*)l4;
        for (int t = npair * 8 + threadIdx.x; t < n; t += NT)
            acc += err_term(s[t], a[t], l[t]);
    }

    // deterministic block tree reduction
    __shared__ float sm[NT];
    sm[threadIdx.x] = acc;
    __syncthreads();
#pragma unroll
    for (int off = NT / 2; off > 0; off >>= 1) {
        if (threadIdx.x < off) sm[threadIdx.x] += sm[threadIdx.x + off];
        __syncthreads();
    }

    __shared__ bool s_last;
    if (threadIdx.x == 0) {
        g_partials[blockIdx.x] = sm[0];
        __threadfence();
        unsigned int prev = atomicAdd(&g_done_count, 1u);
        s_last = (prev == (unsigned int)(gridDim.x - 1));
    }
    __syncthreads();

    if (s_last) {
        __threadfence();  // all partials visible
        float facc = 0.0f;
        for (int k = threadIdx.x; k < NB; k += NT)
            facc += g_partials[k];
        sm[threadIdx.x] = facc;
        __syncthreads();
#pragma unroll
        for (int off = NT / 2; off > 0; off >>= 1) {
            if (threadIdx.x < off) sm[threadIdx.x] += sm[threadIdx.x + off];
            __syncthreads();
        }
        if (threadIdx.x == 0) {
            out[0] = -sm[0] / (float)n;
            g_done_count = 0;   // reset for next graph replay
        }
    }
}

extern "C" void kernel_launch(void* const* d_in, const int* in_sizes, int n_in,
                              void* d_out, int out_size)
{
    const float* s   = (const float*)d_in[0];  // synonymy_score [B]
    const float* a   = (const float*)d_in[1];  // antonymy_score [B]
    const int*   lab = (const int*)d_in[2];    // labels [B] (int32 on device)
    float*       out = (float*)d_out;

    const int n    = in_sizes[0];
    const int nvec = n / 4;

    loss_fused_kernel<<<NB, NT>>>((const float4*)s, (const float4*)a,
                                  (const int4*)lab, out, n, nvec);
}